// round 12
// baseline (speedup 1.0000x reference)
#include <cuda_runtime.h>
#include <cuda_bf16.h>

// Shapes (fixed):
//   emb_nodes : [B=4, N=768, d=16] f32   (d_in[0])
//   edges     : [B=4, 2, E=12288]  i32   (d_in[1])
//   W         : [32] f32                 (d_in[2])
//   b         : [1]  f32                 (d_in[3])
// d_out (f32): ee [4,589824,32] @0 | logits [4,589824] @75497472 | truth @77856768

namespace {
constexpr unsigned B_  = 4;
constexpr unsigned N_  = 768;
constexpr unsigned E_  = 12288;
constexpr unsigned NN_    = N_ * N_;          // 589824
constexpr unsigned PAIRS_ = B_ * NN_;         // 2359296
constexpr unsigned NODES_ = B_ * N_;          // 3072
constexpr unsigned BM_WORDS_ = PAIRS_ / 32;   // 73728 (288 KB bitmap)
constexpr unsigned long long EE_ELEMS_ = (unsigned long long)PAIRS_ * 32; // 75497472
}

// Ground-truth edge bitmap. Zero-initialized at module load; every
// kernel_launch leaves it zero again (mega clears its own words after
// reading), so graph replays are deterministic.
__device__ unsigned g_bitmap[BM_WORDS_];

// ---------------------------------------------------------------------------
// Kernel 1: scatter edges into the bitmap (L2-resident, atomicOr).
// ---------------------------------------------------------------------------
__global__ __launch_bounds__(256)
void edge_bitmap_kernel(const int* __restrict__ edges)
{
    unsigned t = blockIdx.x * blockDim.x + threadIdx.x;
    if (t >= B_ * E_) return;
    unsigned b = t / E_;
    unsigned e = t - b * E_;
    unsigned src = (unsigned)edges[b * 2 * E_ + e];
    unsigned dst = (unsigned)edges[b * 2 * E_ + E_ + e];
    unsigned pair = b * NN_ + src * N_ + dst;
    atomicOr(&g_bitmap[pair >> 5], 1u << (pair & 31));
}

// ---------------------------------------------------------------------------
// Kernel 2 (mega): one block per (b,i) row.
//   - writes the row's 96KB edge_embeddings segment (24 float4/thread)
//   - threads 0..191 compute 4 logits each (inline dots + exact == check)
//     and materialize truth from the bitmap, then clear the bitmap words.
// ---------------------------------------------------------------------------
__global__ __launch_bounds__(256)
void mega_kernel(const float4* __restrict__ emb4,
                 const float4* __restrict__ W4,
                 const float*  __restrict__ bias,
                 float4* __restrict__ ee4,
                 float4* __restrict__ logits4,
                 float4* __restrict__ truth4)
{
    unsigned blk = blockIdx.x;            // b*768 + i
    unsigned tid = threadIdx.x;

    // row i in registers
    float4 ri0 = __ldg(emb4 + blk * 4u + 0);
    float4 ri1 = __ldg(emb4 + blk * 4u + 1);
    float4 ri2 = __ldg(emb4 + blk * 4u + 2);
    float4 ri3 = __ldg(emb4 + blk * 4u + 3);

    unsigned b = blk / N_;
    const float4* embB = emb4 + b * N_ * 4u;
    float4* dst = ee4 + (unsigned long long)blk * (N_ * 8u);   // 6144 float4

    // ---- edge_embeddings: 6144 float4 / 256 threads = 24 each ----
    #pragma unroll 8
    for (unsigned it = 0; it < 24; ++it) {
        unsigned f     = it * 256u + tid;
        unsigned j     = f >> 3;
        unsigned chunk = f & 7u;
        float4 v;
        if (chunk < 4) {
            v = (chunk == 0) ? ri0 : (chunk == 1) ? ri1 : (chunk == 2) ? ri2 : ri3;
        } else {
            v = __ldg(embB + j * 4u + (chunk - 4u));
        }
        __stcs(dst + f, v);
    }

    // ---- logits + truth: 768 pairs -> threads 0..191, 4 pairs each ----
    if (tid < N_ / 4) {
        float4 w1[4], w2[4];
        #pragma unroll
        for (int c = 0; c < 4; ++c) { w1[c] = __ldg(W4 + c); w2[c] = __ldg(W4 + c + 4); }

        // dot1(i) + bias
        float d1 = __ldg(bias);
        d1 = fmaf(ri0.x, w1[0].x, d1); d1 = fmaf(ri0.y, w1[0].y, d1);
        d1 = fmaf(ri0.z, w1[0].z, d1); d1 = fmaf(ri0.w, w1[0].w, d1);
        d1 = fmaf(ri1.x, w1[1].x, d1); d1 = fmaf(ri1.y, w1[1].y, d1);
        d1 = fmaf(ri1.z, w1[1].z, d1); d1 = fmaf(ri1.w, w1[1].w, d1);
        d1 = fmaf(ri2.x, w1[2].x, d1); d1 = fmaf(ri2.y, w1[2].y, d1);
        d1 = fmaf(ri2.z, w1[2].z, d1); d1 = fmaf(ri2.w, w1[2].w, d1);
        d1 = fmaf(ri3.x, w1[3].x, d1); d1 = fmaf(ri3.y, w1[3].y, d1);
        d1 = fmaf(ri3.z, w1[3].z, d1); d1 = fmaf(ri3.w, w1[3].w, d1);

        const float4 ri[4] = {ri0, ri1, ri2, ri3};
        unsigned j0 = tid * 4u;
        float lg[4];
        #pragma unroll
        for (int q = 0; q < 4; ++q) {
            unsigned j = j0 + q;
            float d2 = 0.f;
            bool eq = true;
            #pragma unroll
            for (int c = 0; c < 4; ++c) {
                float4 rj = __ldg(embB + j * 4u + c);
                d2 = fmaf(rj.x, w2[c].x, d2); d2 = fmaf(rj.y, w2[c].y, d2);
                d2 = fmaf(rj.z, w2[c].z, d2); d2 = fmaf(rj.w, w2[c].w, d2);
                eq = eq && (ri[c].x == rj.x) && (ri[c].y == rj.y)
                        && (ri[c].z == rj.z) && (ri[c].w == rj.w);
            }
            lg[q] = eq ? -10.0f : (d1 + d2);
        }

        unsigned pair0 = blk * N_ + j0;            // first of the 4 pairs
        unsigned widx  = pair0 >> 5;               // bitmap word (block-owned)
        unsigned w     = g_bitmap[widx];
        unsigned bit0  = pair0 & 31u;
        float4 tr = make_float4((float)((w >> (bit0 + 0)) & 1u),
                                (float)((w >> (bit0 + 1)) & 1u),
                                (float)((w >> (bit0 + 2)) & 1u),
                                (float)((w >> (bit0 + 3)) & 1u));

        unsigned q4 = pair0 >> 2;
        __stcs(logits4 + q4, make_float4(lg[0], lg[1], lg[2], lg[3]));
        __stcs(truth4 + q4, tr);

        // clear block-owned bitmap words for the next replay.
        // 8 consecutive threads (same warp) share one word: sync reads first.
        __syncwarp();
        if ((tid & 7u) == 0u) g_bitmap[widx] = 0u;
    }
}

extern "C" void kernel_launch(void* const* d_in, const int* in_sizes, int n_in,
                              void* d_out, int out_size)
{
    const float* emb   = (const float*)d_in[0];
    const int*   edges = (const int*)d_in[1];
    const float* W     = (const float*)d_in[2];
    const float* bias  = (const float*)d_in[3];

    float* out    = (float*)d_out;
    float* ee     = out;
    float* logits = out + EE_ELEMS_;
    float* truth  = out + EE_ELEMS_ + PAIRS_;

    // 1. edge scatter into bitmap (49152 threads)
    edge_bitmap_kernel<<<(B_ * E_) / 256, 256>>>(edges);
    // 2. mega: all 321MB of output + bitmap self-clear
    mega_kernel<<<NODES_, 256>>>((const float4*)emb, (const float4*)W, bias,
                                 (float4*)ee, (float4*)logits, (float4*)truth);
}

// round 14
// speedup vs baseline: 1.5393x; 1.5393x over previous
#include <cuda_runtime.h>
#include <cuda_bf16.h>

// Shapes (fixed):
//   emb_nodes : [B=4, N=768, d=16] f32   (d_in[0])
//   edges     : [B=4, 2, E=12288]  i32   (d_in[1])
//   W         : [32] f32                 (d_in[2])
//   b         : [1]  f32                 (d_in[3])
// d_out (f32): ee [4,589824,32] @0 | logits [4,589824] @75497472 | truth @77856768

namespace {
constexpr unsigned B_  = 4;
constexpr unsigned N_  = 768;
constexpr unsigned E_  = 12288;
constexpr unsigned NN_    = N_ * N_;          // 589824
constexpr unsigned PAIRS_ = B_ * NN_;         // 2359296
constexpr unsigned NODES_ = B_ * N_;          // 3072
constexpr unsigned BM_WORDS_ = PAIRS_ / 32;   // 73728 (288 KB bitmap)
constexpr unsigned long long EE_ELEMS_ = (unsigned long long)PAIRS_ * 32; // 75497472
}

// Device-global scratch (no allocation allowed).
__device__ float    g_dot1[NODES_];     // e_v . W[0:16] + bias
__device__ float    g_dot2[NODES_];     // e_v . W[16:32]
__device__ unsigned g_hash[NODES_];     // row-bit hash (0-canonicalized)
// Ground-truth bitmap: zero at module load; mega self-clears after reading,
// so every kernel_launch starts from zero (graph-replay deterministic).
__device__ unsigned g_bitmap[BM_WORDS_];

// ---------------------------------------------------------------------------
// Kernel 1: edge scatter into bitmap + per-node dots/hash (disjoint ranges).
// 49152 threads; first 3072 also do the node precompute.
// ---------------------------------------------------------------------------
__global__ __launch_bounds__(256)
void scatter_pre_kernel(const int*    __restrict__ edges,
                        const float4* __restrict__ emb4,
                        const float4* __restrict__ W4,
                        const float*  __restrict__ bias)
{
    unsigned t = blockIdx.x * blockDim.x + threadIdx.x;

    if (t < B_ * E_) {
        unsigned b = t / E_;
        unsigned e = t - b * E_;
        unsigned src = (unsigned)edges[b * 2 * E_ + e];
        unsigned dst = (unsigned)edges[b * 2 * E_ + E_ + e];
        unsigned pair = b * NN_ + src * N_ + dst;
        atomicOr(&g_bitmap[pair >> 5], 1u << (pair & 31));
    }

    if (t < NODES_) {
        float d1 = __ldg(bias);
        float d2 = 0.f;
        unsigned h = 0u;
        #pragma unroll
        for (int c = 0; c < 4; ++c) {
            float4 a  = __ldg(emb4 + t * 4u + c);
            float4 w1 = __ldg(W4 + c);
            float4 w2 = __ldg(W4 + c + 4);
            d1 = fmaf(a.x, w1.x, d1); d1 = fmaf(a.y, w1.y, d1);
            d1 = fmaf(a.z, w1.z, d1); d1 = fmaf(a.w, w1.w, d1);
            d2 = fmaf(a.x, w2.x, d2); d2 = fmaf(a.y, w2.y, d2);
            d2 = fmaf(a.z, w2.z, d2); d2 = fmaf(a.w, w2.w, d2);
            const float vals[4] = {a.x, a.y, a.z, a.w};
            #pragma unroll
            for (int k = 0; k < 4; ++k) {
                unsigned u = __float_as_uint(vals[k]);
                if (vals[k] == 0.f) u = 0u;          // canonicalize +-0
                int rot = (c * 4 + k) & 31;
                h ^= __funnelshift_l(u, u, rot);
            }
        }
        g_dot1[t] = d1;
        g_dot2[t] = d2;
        g_hash[t] = h;
    }
}

// exact row comparison under float== (rare path: hash matched)
__device__ __forceinline__ bool rows_equal(const float4* __restrict__ emb4,
                                           unsigned va, unsigned vb)
{
    bool eq = true;
    #pragma unroll
    for (int c = 0; c < 4; ++c) {
        float4 a = __ldg(emb4 + va * 4u + c);
        float4 b = __ldg(emb4 + vb * 4u + c);
        eq = eq && (a.x == b.x) && (a.y == b.y) && (a.z == b.z) && (a.w == b.w);
    }
    return eq;
}

// ---------------------------------------------------------------------------
// Kernel 2 (mega): one block per (b,i) row. Writes the 96KB ee segment;
// threads 0..191 emit the row's 768 logits + truth from the LIGHT
// precomputed scratch (few loads, no W registers), then clear the
// block-owned bitmap words.
// ---------------------------------------------------------------------------
__global__ __launch_bounds__(256)
void mega_kernel(const float4* __restrict__ emb4,
                 float4* __restrict__ ee4,
                 float4* __restrict__ logits4,
                 float4* __restrict__ truth4)
{
    unsigned blk = blockIdx.x;            // b*768 + i
    unsigned tid = threadIdx.x;

    // row i in registers
    float4 ri0 = __ldg(emb4 + blk * 4u + 0);
    float4 ri1 = __ldg(emb4 + blk * 4u + 1);
    float4 ri2 = __ldg(emb4 + blk * 4u + 2);
    float4 ri3 = __ldg(emb4 + blk * 4u + 3);

    unsigned b = blk / N_;
    const float4* embB = emb4 + b * N_ * 4u;
    float4* dst = ee4 + (unsigned long long)blk * (N_ * 8u);   // 6144 float4

    // ---- edge_embeddings: 6144 float4 / 256 threads = 24 each ----
    #pragma unroll 8
    for (unsigned it = 0; it < 24; ++it) {
        unsigned f     = it * 256u + tid;
        unsigned j     = f >> 3;
        unsigned chunk = f & 7u;
        float4 v;
        if (chunk < 4) {
            v = (chunk == 0) ? ri0 : (chunk == 1) ? ri1 : (chunk == 2) ? ri2 : ri3;
        } else {
            v = __ldg(embB + j * 4u + (chunk - 4u));
        }
        __stcs(dst + f, v);
    }

    // ---- logits + truth: 768 pairs -> threads 0..191, 4 pairs each ----
    if (tid < N_ / 4) {
        unsigned j0 = tid * 4u;
        unsigned ni = blk;
        float    d1 = g_dot1[ni];
        unsigned hi = g_hash[ni];

        unsigned nj = b * N_ + j0;
        float4 d2 = *(const float4*)&g_dot2[nj];
        uint4  hj = *(const uint4*)&g_hash[nj];

        float lg[4] = { d1 + d2.x, d1 + d2.y, d1 + d2.z, d1 + d2.w };
        const unsigned hjs[4] = { hj.x, hj.y, hj.z, hj.w };
        #pragma unroll
        for (int q = 0; q < 4; ++q) {
            if (hi == hjs[q]) {                    // rare: verify exactly
                if (rows_equal(emb4, ni, nj + q)) lg[q] = -10.0f;
            }
        }

        unsigned pair0 = blk * N_ + j0;            // first of the 4 pairs
        unsigned widx  = pair0 >> 5;               // bitmap word (block-owned)
        unsigned w     = g_bitmap[widx];
        unsigned bit0  = pair0 & 31u;
        float4 tr = make_float4((float)((w >> (bit0 + 0)) & 1u),
                                (float)((w >> (bit0 + 1)) & 1u),
                                (float)((w >> (bit0 + 2)) & 1u),
                                (float)((w >> (bit0 + 3)) & 1u));

        unsigned q4 = pair0 >> 2;
        __stcs(logits4 + q4, make_float4(lg[0], lg[1], lg[2], lg[3]));
        __stcs(truth4 + q4, tr);

        // clear block-owned bitmap words for the next replay.
        // 8 consecutive threads (same warp) share one word: sync reads first.
        __syncwarp();
        if ((tid & 7u) == 0u) g_bitmap[widx] = 0u;
    }
}

extern "C" void kernel_launch(void* const* d_in, const int* in_sizes, int n_in,
                              void* d_out, int out_size)
{
    const float* emb   = (const float*)d_in[0];
    const int*   edges = (const int*)d_in[1];
    const float* W     = (const float*)d_in[2];
    const float* bias  = (const float*)d_in[3];

    float* out    = (float*)d_out;
    float* ee     = out;
    float* logits = out + EE_ELEMS_;
    float* truth  = out + EE_ELEMS_ + PAIRS_;

    // 1. fused edge scatter + node precompute (49152 threads)
    scatter_pre_kernel<<<(B_ * E_) / 256, 256>>>(edges, (const float4*)emb,
                                                 (const float4*)W, bias);
    // 2. mega: all 321MB of output + bitmap self-clear
    mega_kernel<<<NODES_, 256>>>((const float4*)emb, (float4*)ee,
                                 (float4*)logits, (float4*)truth);
}